// round 13
// baseline (speedup 1.0000x reference)
#include <cuda_runtime.h>
#include <cuda_bf16.h>
#include <cstdint>

// Problem constants
#define TT   1024
#define BB   32
#define NH   8
#define DD   32
#define YD   97
#define INDIM 256          // NH*DD
#define ROWSTRIDE 8192     // BB*INDIM

typedef unsigned long long u64;

// -------- scratch (device globals; no allocation allowed) ----------
__device__ float g_fwm[(size_t)TT * BB * INDIM];   // FWM output pre-GEMM, 33.5 MB

// -------- packed f32x2 helpers ----------
__device__ __forceinline__ u64 ffma2(u64 a, u64 b, u64 c) {
    u64 d;
    asm("fma.rn.f32x2 %0, %1, %2, %3;" : "=l"(d) : "l"(a), "l"(b), "l"(c));
    return d;
}
__device__ __forceinline__ u64 add2(u64 a, u64 b) {
    u64 d;
    asm("add.rn.f32x2 %0, %1, %2;" : "=l"(d) : "l"(a), "l"(b));
    return d;
}
__device__ __forceinline__ u64 pack2(float a, float b) {
    u64 r;
    asm("mov.b64 %0, {%1, %2};" : "=l"(r) : "f"(a), "f"(b));
    return r;
}
__device__ __forceinline__ u64 bcast2(float a) {
    u64 r;
    asm("mov.b64 %0, {%1, %1};" : "=l"(r) : "f"(a));
    return r;
}
__device__ __forceinline__ float hsum2(u64 v) {
    float a, b;
    asm("mov.b64 {%0, %1}, %2;" : "=f"(a), "=f"(b) : "l"(v));
    return a + b;
}

// float4 viewed as two packed f32x2
union f4u {
    float4 f;
    u64    u[2];
};
__device__ __forceinline__ f4u ld4(const float* p) {
    f4u r;
    r.f = *(const float4*)p;   // LDS.128
    return r;
}

// -------- warp sum (5-round SHFL butterfly) ----
__device__ __forceinline__ float wsum(float v) {
#pragma unroll
    for (int o = 16; o; o >>= 1) v += __shfl_xor_sync(0xffffffffu, v, o);
    return v;
}

__device__ __forceinline__ float hsum4(const u64* a) {
    return hsum2(add2(add2(a[0], a[1]), add2(a[2], a[3])));
}

// -------- dot(x[0:32], column) via 8 LDS.128 + 16 FFMA2 (peel only) --------
__device__ __forceinline__ float dot32v(const float* __restrict__ xp, const u64* c) {
    u64 a0 = 0ull, a1 = 0ull, a2 = 0ull, a3 = 0ull;
#pragma unroll
    for (int i = 0; i < 4; i++) {
        f4u x0 = ld4(xp + 8 * i);
        f4u x1 = ld4(xp + 8 * i + 4);
        a0 = ffma2(x0.u[0], c[4 * i],     a0);
        a1 = ffma2(x0.u[1], c[4 * i + 1], a1);
        a2 = ffma2(x1.u[0], c[4 * i + 2], a2);
        a3 = ffma2(x1.u[1], c[4 * i + 3], a3);
    }
    return hsum2(add2(add2(a0, a1), add2(a2, a3)));
}

// ======================================================================
// Kernel 1: fused softmax(h) + SRWM + FWM recurrence. One CTA per (b,h).
// 8 warps: w0 fq, w1 fk, w2 fv, w3 wb (beta/fb), w4 q, w5 k (+sxk publish),
// w6 FWM, w7 x staging with a 2-deep LDG prefetch pipeline (two intervals
// of slack so the strided DRAM load never stalls the barrier).
// ======================================================================
__global__ __launch_bounds__(256, 2)
void srwm_kernel(const float* __restrict__ h,
                 const float* __restrict__ W_y, const float* __restrict__ W_q,
                 const float* __restrict__ W_k, const float* __restrict__ w_b,
                 const float* __restrict__ sW_y, const float* __restrict__ sW_q,
                 const float* __restrict__ sW_k, const float* __restrict__ sw_b,
                 const float* __restrict__ F0) {
    __shared__ __align__(16) float xs[3][DD];                 // x ring
    __shared__ __align__(16) float q_s[2][DD], k_s[2][DD];
    __shared__ __align__(16) float fq_s[2][DD], fk_s[2][DD], fv_s[2][DD];
    __shared__ __align__(16) float beta_s[2][4];
    __shared__ float fb_s[2];
    __shared__ float sxk_s[2];                                // published x.k

    const int bh   = blockIdx.x;           // b*NH + h
    const int hh   = bh & (NH - 1);
    const int tid  = threadIdx.x;
    const int warp = tid >> 5;
    const int lane = tid & 31;

    // ---- role / column assignment ----
    int role, e;
    if (warp < 3)            { role = 0; e = warp * 32 + lane; }
    else if (warp == 3) {
        if (lane == 0)       { role = 0; e = 96; }
        else                 { role = 1; e = (lane - 1) & 3; }
    }
    else if (warp == 4)      { role = 2; e = lane; }
    else if (warp == 5)      { role = 3; e = lane; }
    else if (warp == 6)      { role = 4; e = lane; }
    else                     { role = 5; e = lane; }

    const int bidx = (role == 0) ? 0 : (role == 2) ? 1 : (role == 3) ? 2 : 3;

    // ---- initial column load (state + broadcast weight) ----
    u64 c[16];
#pragma unroll
    for (int i = 0; i < 16; i++) c[i] = 0ull;
    if (role <= 4) {
        const float* sp;
        const float* wp = nullptr;
        int stride;
        switch (role) {
            case 0: sp = sW_y + (size_t)bh * DD * YD + e; wp = W_y + (size_t)hh * DD * YD + e; stride = YD; break;
            case 1: sp = sw_b + (size_t)bh * DD * 4  + e; wp = w_b + (size_t)hh * DD * 4  + e; stride = 4;  break;
            case 2: sp = sW_q + (size_t)bh * DD * DD + e; wp = W_q + (size_t)hh * DD * DD + e; stride = DD; break;
            case 3: sp = sW_k + (size_t)bh * DD * DD + e; wp = W_k + (size_t)hh * DD * DD + e; stride = DD; break;
            default: sp = F0  + (size_t)bh * DD * DD + e;                                       stride = DD; break;
        }
#pragma unroll
        for (int i = 0; i < 16; i++) {
            float v0 = sp[(2 * i)     * stride];
            float v1 = sp[(2 * i + 1) * stride];
            if (wp) { v0 += wp[(2 * i) * stride]; v1 += wp[(2 * i + 1) * stride]; }
            c[i] = pack2(v0, v1);
        }
    }

    // ---- prologue: warp 7 stages x0, x1; fills 2-deep prefetch pipe ----
    const float* hrow = h + (size_t)bh * DD + lane;
    float xr0 = 0.0f, xr1 = 0.0f;
    float* gout = g_fwm + (size_t)bh * DD + lane;
    if (role == 5) {
        float p0 = __expf(hrow[0]);
        float s0 = wsum(p0);
        xs[0][lane] = __fdividef(p0, s0);
        float p1 = __expf(hrow[ROWSTRIDE]);
        float s1 = wsum(p1);
        xs[1][lane] = __fdividef(p1, s1);
        xr0 = hrow[(size_t)2 * ROWSTRIDE];
        xr1 = hrow[(size_t)3 * ROWSTRIDE];
    }
    __syncthreads();

    // ---- peeled interval t = 0: matvec only; warp5 also publishes sxk(1) ----
    if (role <= 3) {
        float yv = dot32v(xs[0], c);
        if (warp == 0)      { float p = __expf(yv); float s = wsum(p); fq_s[0][lane] = __fdividef(p, s); }
        else if (warp == 1) { float p = __expf(yv); float s = wsum(p); fk_s[0][lane] = __fdividef(p, s); }
        else if (warp == 2) { fv_s[0][lane] = yv; }
        else if (warp == 3) { float sg = __fdividef(1.0f, 1.0f + __expf(-yv));
                              if (lane == 0) fb_s[0] = sg;
                              else if (lane <= 4) beta_s[0][e] = sg; }
        else if (warp == 4) { float p = __expf(yv); float s = wsum(p); q_s[0][lane] = __fdividef(p, s); }
        else                { float p = __expf(yv); float s = wsum(p);
                              float kval = __fdividef(p, s);
                              k_s[0][lane] = kval;
                              float sx = wsum(xs[1][lane] * kval);     // sxk for t=1
                              if (lane == 0) sxk_s[1] = sx; }
    } else if (role == 5) {
        float p = __expf(xr0);
        float s = wsum(p);
        xs[2][lane] = __fdividef(p, s);
        xr0 = xr1;
        xr1 = hrow[(size_t)4 * ROWSTRIDE];
    }
    __syncthreads();

    const u64 neg1 = bcast2(-1.0f);

    // x-ring slot indices for interval t: read xi_r = t%3, next xi_n = (t+1)%3,
    // write xi_w = (t+2)%3. Rotation: (r,n,w) <- (n,w,r).
    int xi_r = 1, xi_n = 2, xi_w = 0;

    // ================= time loop: one barrier per interval =================
    for (int t = 1; t < TT; t++) {
        const int pm = (t - 1) & 1;   // buffers from interval t-1
        const int pc = t & 1;         // buffers produced this interval

        if (role <= 3) {
            const float* qp = q_s[pm];
            const float* kp = k_s[pm];
            const float* xp = xs[xi_r];
            float sxk = sxk_s[pc];                 // published last interval
            float bi  = beta_s[pm][bidx];

            // parallel dots on c_old: (q-k)·c and x·c ; keep k for update
            u64 kv[16];
            u64 ad[4] = {0ull, 0ull, 0ull, 0ull};
            u64 ax[4] = {0ull, 0ull, 0ull, 0ull};
#pragma unroll
            for (int i = 0; i < 8; i++) {
                f4u qv = ld4(qp + 4 * i);
                f4u kk = ld4(kp + 4 * i);
                f4u xv = ld4(xp + 4 * i);
                u64 dm0 = ffma2(kk.u[0], neg1, qv.u[0]);   // q - k
                u64 dm1 = ffma2(kk.u[1], neg1, qv.u[1]);
                ad[(2 * i)     & 3] = ffma2(dm0, c[2 * i],     ad[(2 * i)     & 3]);
                ad[(2 * i + 1) & 3] = ffma2(dm1, c[2 * i + 1], ad[(2 * i + 1) & 3]);
                ax[(2 * i)     & 3] = ffma2(xv.u[0], c[2 * i],     ax[(2 * i)     & 3]);
                ax[(2 * i + 1) & 3] = ffma2(xv.u[1], c[2 * i + 1], ax[(2 * i + 1) & 3]);
                kv[2 * i]     = kk.u[0];
                kv[2 * i + 1] = kk.u[1];
            }
            float delta = bi * hsum4(ad);
            float yv    = hsum4(ax) + delta * sxk;

            // activations / publication (critical path) first
            if (warp == 0)      { float p = __expf(yv); float s = wsum(p); fq_s[pc][lane] = __fdividef(p, s); }
            else if (warp == 1) { float p = __expf(yv); float s = wsum(p); fk_s[pc][lane] = __fdividef(p, s); }
            else if (warp == 2) { fv_s[pc][lane] = yv; }
            else if (warp == 3) { float sg = __fdividef(1.0f, 1.0f + __expf(-yv));
                                  if (lane == 0) fb_s[pc] = sg;
                                  else if (lane <= 4) beta_s[pc][e] = sg; }
            else if (warp == 4) { float p = __expf(yv); float s = wsum(p); q_s[pc][lane] = __fdividef(p, s); }
            else                { float p = __expf(yv); float s = wsum(p);
                                  float kval = __fdividef(p, s);
                                  k_s[pc][lane] = kval;
                                  // publish sxk for interval t+1: x_{t+1} . k_t
                                  float sx = wsum(xs[xi_n][lane] * kval);
                                  if (lane == 0) sxk_s[pm] = sx; }   // (t+1)&1 == pm

            // off-path state update
            u64 d2 = bcast2(delta);
#pragma unroll
            for (int i = 0; i < 16; i++) c[i] = ffma2(kv[i], d2, c[i]);
        } else if (role == 4) {
            // ---- warp 6: FWM step t-1 ----
            const float* fqp = fq_s[pm];
            const float* fkp = fk_s[pm];
            float sqk = wsum(fqp[lane] * fkp[lane]);
            float fb  = fb_s[pm];
            float fvd = fv_s[pm][lane];

            u64 kv[16];
            u64 av[4] = {0ull, 0ull, 0ull, 0ull};
            u64 ao[4] = {0ull, 0ull, 0ull, 0ull};
#pragma unroll
            for (int i = 0; i < 8; i++) {
                f4u fqv = ld4(fqp + 4 * i);
                f4u fkv = ld4(fkp + 4 * i);
                av[(2 * i)     & 3] = ffma2(fkv.u[0], c[2 * i],     av[(2 * i)     & 3]);
                av[(2 * i + 1) & 3] = ffma2(fkv.u[1], c[2 * i + 1], av[(2 * i + 1) & 3]);
                ao[(2 * i)     & 3] = ffma2(fqv.u[0], c[2 * i],     ao[(2 * i)     & 3]);
                ao[(2 * i + 1) & 3] = ffma2(fqv.u[1], c[2 * i + 1], ao[(2 * i + 1) & 3]);
                kv[2 * i]     = fkv.u[0];
                kv[2 * i + 1] = fkv.u[1];
            }
            float vold = hsum4(av);
            float outq = hsum4(ao);
            float delta = fb * (fvd - vold);
            gout[(size_t)(t - 1) * ROWSTRIDE] = outq + delta * sqk;
            u64 d2 = bcast2(delta);
#pragma unroll
            for (int i = 0; i < 16; i++) c[i] = ffma2(kv[i], d2, c[i]);
        } else {
            // ---- warp 7: stage x_{t+2}; keep 2 loads in flight ----
            if (t + 2 < TT) {
                float p = __expf(xr0);
                float s = wsum(p);
                xs[xi_w][lane] = __fdividef(p, s);
                xr0 = xr1;
                xr1 = (t + 4 < TT) ? hrow[(size_t)(t + 4) * ROWSTRIDE] : 0.0f;
            }
        }
        // rotate ring indices
        int tmp = xi_r; xi_r = xi_n; xi_n = xi_w; xi_w = tmp;
        __syncthreads();
    }

    // ---- epilogue: FWM step TT-1 ----
    if (role == 4) {
        const int pm = (TT - 1) & 1;
        const float* fqp = fq_s[pm];
        const float* fkp = fk_s[pm];
        float sqk = wsum(fqp[lane] * fkp[lane]);
        u64 av[4] = {0ull, 0ull, 0ull, 0ull};
        u64 ao[4] = {0ull, 0ull, 0ull, 0ull};
#pragma unroll
        for (int i = 0; i < 8; i++) {
            f4u fqv = ld4(fqp + 4 * i);
            f4u fkv = ld4(fkp + 4 * i);
            av[(2 * i)     & 3] = ffma2(fkv.u[0], c[2 * i],     av[(2 * i)     & 3]);
            av[(2 * i + 1) & 3] = ffma2(fkv.u[1], c[2 * i + 1], av[(2 * i + 1) & 3]);
            ao[(2 * i)     & 3] = ffma2(fqv.u[0], c[2 * i],     ao[(2 * i)     & 3]);
            ao[(2 * i + 1) & 3] = ffma2(fqv.u[1], c[2 * i + 1], ao[(2 * i + 1) & 3]);
        }
        float vold = hsum4(av);
        float outq = hsum4(ao);
        float delta = fb_s[pm] * (fv_s[pm][lane] - vold);
        gout[(size_t)(TT - 1) * ROWSTRIDE] = outq + delta * sqk;
    }
}

// ======================================================================
// Kernel 2: out = h + g_fwm @ W_out^T    (M=32768, N=256, K=256)
// ======================================================================
#define GBM 128
#define GBN 64
#define GBK 32
#define ALDA (GBM + 4)
#define BLDA (GBN + 4)

__global__ __launch_bounds__(256)
void out_gemm_kernel(const float* __restrict__ W,   // W_out [n][k], 256x256
                     const float* __restrict__ h,
                     float* __restrict__ out) {
    __shared__ __align__(16) float As[2][GBK][ALDA];
    __shared__ __align__(16) float Bs[2][GBK][BLDA];

    const int tid = threadIdx.x;
    const int m0  = blockIdx.x * GBM;
    const int n0  = blockIdx.y * GBN;
    const int ty  = tid >> 4;
    const int tx  = tid & 15;

    const int a_row = tid >> 3;
    const int a_kv  = (tid & 7) * 4;
    const int b_row = tid >> 3;
    const int b_kv  = (tid & 7) * 4;

    u64 acc[8][2];
#pragma unroll
    for (int i = 0; i < 8; i++) { acc[i][0] = 0ull; acc[i][1] = 0ull; }

    const int NT = INDIM / GBK;

    float4 ar[4], br[2];
#pragma unroll
    for (int r = 0; r < 4; r++)
        ar[r] = *(const float4*)(g_fwm + (size_t)(m0 + a_row + r * 32) * INDIM + a_kv);
#pragma unroll
    for (int r = 0; r < 2; r++)
        br[r] = *(const float4*)(W + (size_t)(n0 + b_row + r * 32) * INDIM + b_kv);
#pragma unroll
    for (int r = 0; r < 4; r++) {
        int row = a_row + r * 32;
        As[0][a_kv + 0][row] = ar[r].x; As[0][a_kv + 1][row] = ar[r].y;
        As[0][a_kv + 2][row] = ar[r].z; As[0][a_kv + 3][row] = ar[r].w;
    }
#pragma unroll
    for (int r = 0; r < 2; r++) {
        int row = b_row + r * 32;
        Bs[0][b_kv + 0][row] = br[r].x; Bs[0][b_kv + 1][row] = br[r].y;
        Bs[0][b_kv + 2][row] = br[r].z; Bs[0][b_kv + 3][row] = br[r].w;
    }
    __syncthreads();

    for (int kt = 0; kt < NT; kt++) {
        const int s = kt & 1;
        if (kt + 1 < NT) {
            const int ko = (kt + 1) * GBK;
#pragma unroll
            for (int r = 0; r < 4; r++)
                ar[r] = *(const float4*)(g_fwm + (size_t)(m0 + a_row + r * 32) * INDIM + ko + a_kv);
#pragma unroll
            for (int r = 0; r < 2; r++)
                br[r] = *(const float4*)(W + (size_t)(n0 + b_row + r * 32) * INDIM + ko + b_kv);
        }
#pragma unroll
        for (int k = 0; k < GBK; k++) {
            f4u a0 = ld4(&As[s][k][ty * 8]);
            f4u a1 = ld4(&As[s][k][ty * 8 + 4]);
            f4u b  = ld4(&Bs[s][k][tx * 4]);
            u64 p;
            float av[8];
            av[0] = a0.f.x; av[1] = a0.f.y; av[2] = a0.f.z; av[3] = a0.f.w;
            av[4] = a1.f.x; av[5] = a1.f.y; av[6] = a1.f.z; av[7] = a1.f.w;
#pragma unroll
            for (int i = 0; i < 8; i++) {
                p = bcast2(av[i]);
                acc[i][0] = ffma2(p, b.u[0], acc[i][0]);
                acc[i][1] = ffma2(p, b.u[1], acc[i][1]);
            }
        }
        if (kt + 1 < NT) {
            const int d = s ^ 1;
#pragma unroll
            for (int r = 0; r < 4; r++) {
                int row = a_row + r * 32;
                As[d][a_kv + 0][row] = ar[r].x; As[d][a_kv + 1][row] = ar[r].y;
                As[d][a_kv + 2][row] = ar[r].z; As[d][a_kv + 3][row] = ar[r].w;
            }
#pragma unroll
            for (int r = 0; r < 2; r++) {
                int row = b_row + r * 32;
                Bs[d][b_kv + 0][row] = br[r].x; Bs[d][b_kv + 1][row] = br[r].y;
                Bs[d][b_kv + 2][row] = br[r].z; Bs[d][b_kv + 3][row] = br[r].w;
            }
            __syncthreads();
        }
    }

#pragma unroll
    for (int i = 0; i < 8; i++) {
        int row = m0 + ty * 8 + i;
        const float* hp = h + (size_t)row * INDIM + n0 + tx * 4;
        float4 hv = *(const float4*)hp;
        float a, b, cc, d;
        asm("mov.b64 {%0, %1}, %2;" : "=f"(a), "=f"(b) : "l"(acc[i][0]));
        asm("mov.b64 {%0, %1}, %2;" : "=f"(cc), "=f"(d) : "l"(acc[i][1]));
        float4 o;
        o.x = hv.x + a; o.y = hv.y + b; o.z = hv.z + cc; o.w = hv.w + d;
        *(float4*)(out + (size_t)row * INDIM + n0 + tx * 4) = o;
    }
}

// ======================================================================
extern "C" void kernel_launch(void* const* d_in, const int* in_sizes, int n_in,
                              void* d_out, int out_size) {
    const float* h     = (const float*)d_in[0];
    const float* W_y   = (const float*)d_in[1];
    const float* W_q   = (const float*)d_in[2];
    const float* W_k   = (const float*)d_in[3];
    const float* w_b   = (const float*)d_in[4];
    const float* W_out = (const float*)d_in[5];
    const float* sW_y  = (const float*)d_in[6];
    const float* sW_q  = (const float*)d_in[7];
    const float* sW_k  = (const float*)d_in[8];
    const float* sw_b  = (const float*)d_in[9];
    const float* F0    = (const float*)d_in[10];
    float* out = (float*)d_out;

    srwm_kernel<<<BB * NH, 256>>>(h, W_y, W_q, W_k, w_b, sW_y, sW_q, sW_k, sw_b, F0);

    dim3 ggrid((TT * BB) / GBM, INDIM / GBN);
    out_gemm_kernel<<<ggrid, 256>>>(W_out, h, out);
}